// round 3
// baseline (speedup 1.0000x reference)
#include <cuda_runtime.h>
#include <cuda_fp16.h>

#define BB   8
#define SS   4096
#define HH   2048
#define DHH  64
#define KSEL 256

// scratch (no cudaMalloc allowed)
__device__ float d_logits[BB * SS];
__device__ int   d_sel[BB * KSEL];

__device__ __forceinline__ void fma2(unsigned long long& c,
                                     unsigned long long a,
                                     unsigned long long b) {
    asm("fma.rn.f32x2 %0, %1, %2, %0;" : "+l"(c) : "l"(a), "l"(b));
}

// fp32 value rounded through fp16 (matches reference .astype(float16) viewed as fp32)
__device__ __forceinline__ float h16(float v) {
    return __half2float(__float2half_rn(v));
}

// ============================================================================
// Kernel 1: fused logits GEMM (fp32 via packed f32x2 FMA) + fp16-rounded
// fp32 output of hidden_states.
// C[32768,64] = hs[32768,2048] * w1[2048,64]; logit = relu(C+b1)·w2 + b2
// Block: 128 threads, tile BM=128 tokens x full N=64, K-chunk 32.
// ============================================================================
constexpr int BM = 128, BK = 32;

__global__ __launch_bounds__(128, 4)
void k_gemm(const float* __restrict__ hs, const float* __restrict__ w1,
            const float* __restrict__ b1, const float* __restrict__ w2,
            const float* __restrict__ b2, float* __restrict__ out)
{
    __shared__ float2 a_s[BM][BK + 1];   // duplicated values, padded stride
    __shared__ float  b_s[BK][DHH];

    const int tid  = threadIdx.x;
    const int tx   = tid & 7;
    const int ty   = tid >> 3;
    const int tok0 = blockIdx.x * BM;

    unsigned long long acc[8][4];
#pragma unroll
    for (int j = 0; j < 8; j++)
#pragma unroll
        for (int i = 0; i < 4; i++) acc[j][i] = 0ull;

    for (int k0 = 0; k0 < HH; k0 += BK) {
        // stage A (128 x 32 fp32) + write fp16-rounded fp32 output
#pragma unroll
        for (int it = 0; it < 8; it++) {
            int idx = it * 128 + tid;
            int row = idx >> 3;
            int kk  = (idx & 7) << 2;
            const float4 v = *reinterpret_cast<const float4*>(
                hs + (size_t)(tok0 + row) * HH + k0 + kk);
            float4 ov = make_float4(h16(v.x), h16(v.y), h16(v.z), h16(v.w));
            *reinterpret_cast<float4*>(
                out + (size_t)(tok0 + row) * HH + k0 + kk) = ov;
            a_s[row][kk + 0] = make_float2(v.x, v.x);
            a_s[row][kk + 1] = make_float2(v.y, v.y);
            a_s[row][kk + 2] = make_float2(v.z, v.z);
            a_s[row][kk + 3] = make_float2(v.w, v.w);
        }
        // stage B (32 x 64 fp32)
#pragma unroll
        for (int it = 0; it < 4; it++) {
            int f  = (it * 128 + tid) * 4;
            int kk = f >> 6, c = f & 63;
            *reinterpret_cast<float4*>(&b_s[kk][c]) =
                *reinterpret_cast<const float4*>(w1 + (size_t)(k0 + kk) * DHH + c);
        }
        __syncthreads();

#pragma unroll
        for (int kk = 0; kk < BK; kk++) {
            unsigned long long bv[4];
            const unsigned long long* brow =
                reinterpret_cast<const unsigned long long*>(&b_s[kk][tx * 8]);
            bv[0] = brow[0]; bv[1] = brow[1]; bv[2] = brow[2]; bv[3] = brow[3];
#pragma unroll
            for (int j = 0; j < 8; j++) {
                unsigned long long av =
                    *reinterpret_cast<const unsigned long long*>(&a_s[j * 16 + ty][kk]);
                fma2(acc[j][0], av, bv[0]);
                fma2(acc[j][1], av, bv[1]);
                fma2(acc[j][2], av, bv[2]);
                fma2(acc[j][3], av, bv[3]);
            }
        }
        __syncthreads();
    }

    // epilogue: relu + dot w2, reduce 8 col-groups across tx lanes
    float b1v[8], w2v[8];
#pragma unroll
    for (int i = 0; i < 8; i++) { b1v[i] = b1[tx * 8 + i]; w2v[i] = w2[tx * 8 + i]; }
    const float b2v = b2[0];

#pragma unroll
    for (int j = 0; j < 8; j++) {
        float p = 0.f;
#pragma unroll
        for (int i = 0; i < 4; i++) {
            float lo = __uint_as_float((unsigned)(acc[j][i] & 0xffffffffull));
            float hi = __uint_as_float((unsigned)(acc[j][i] >> 32));
            p += fmaxf(lo + b1v[2 * i],     0.f) * w2v[2 * i]
               + fmaxf(hi + b1v[2 * i + 1], 0.f) * w2v[2 * i + 1];
        }
        p += __shfl_xor_sync(0xffffffffu, p, 1);
        p += __shfl_xor_sync(0xffffffffu, p, 2);
        p += __shfl_xor_sync(0xffffffffu, p, 4);
        if (tx == 0) d_logits[tok0 + j * 16 + ty] = p + b2v;
    }
}

// ============================================================================
// Kernel 2: per-batch gumbel top-k (full bitonic sort, matches jax.lax.top_k
// descending order + stable lowest-index tiebreak) + logsumexp + log_prob.
// ============================================================================
__global__ __launch_bounds__(512)
void k_topk(const float* __restrict__ noise, float* __restrict__ out,
            int write_extras)
{
    const int b   = blockIdx.x;
    const int tid = threadIdx.x;
    __shared__ unsigned long long keys[SS];
    __shared__ float red[512];

    const float* lg = d_logits + b * SS;
    const float* nu = noise    + b * SS;

    // build sort keys: (ordered-float score) << 32 | ~index  (desc score, asc idx)
    float m = -3.4e38f;
    for (int i = tid; i < SS; i += 512) {
        float l = lg[i];
        float s = l - logf(-logf(nu[i]));          // logit + gumbel
        unsigned u = __float_as_uint(s);
        u = (u & 0x80000000u) ? ~u : (u | 0x80000000u);
        keys[i] = ((unsigned long long)u << 32) | (unsigned)(~(unsigned)i);
        m = fmaxf(m, l);
    }
    // logsumexp over logits
    red[tid] = m; __syncthreads();
    for (int s2 = 256; s2 > 0; s2 >>= 1) {
        if (tid < s2) red[tid] = fmaxf(red[tid], red[tid + s2]);
        __syncthreads();
    }
    m = red[0]; __syncthreads();
    float sum = 0.f;
    for (int i = tid; i < SS; i += 512) sum += expf(lg[i] - m);
    red[tid] = sum; __syncthreads();
    for (int s2 = 256; s2 > 0; s2 >>= 1) {
        if (tid < s2) red[tid] += red[tid + s2];
        __syncthreads();
    }
    const float lse = m + logf(red[0]);
    __syncthreads();

    // bitonic sort, overall descending
    for (int size = 2; size <= SS; size <<= 1) {
        for (int stride = size >> 1; stride > 0; stride >>= 1) {
            for (int t = tid; t < SS / 2; t += 512) {
                int i = 2 * t - (t & (stride - 1));
                int j = i + stride;
                bool desc = ((i & size) == 0);
                unsigned long long a = keys[i], c = keys[j];
                bool sw = desc ? (a < c) : (a > c);
                if (sw) { keys[i] = c; keys[j] = a; }
            }
            __syncthreads();
        }
    }

    // emit top-K
    float lp = 0.f;
    for (int kk = tid; kk < KSEL; kk += 512) {
        int idx = (int)(~(unsigned)(keys[kk] & 0xffffffffull));
        d_sel[b * KSEL + kk] = idx;
        lp += lg[idx] - lse;
        if (write_extras) {
            out[(size_t)BB * SS * HH + b * KSEL + kk] = (float)idx;           // indices
            out[(size_t)BB * SS * HH + BB * KSEL + b * KSEL + kk] = 1.0f;     // types
        }
    }
    red[tid] = lp; __syncthreads();
    for (int s2 = 256; s2 > 0; s2 >>= 1) {
        if (tid < s2) red[tid] += red[tid + s2];
        __syncthreads();
    }
    if (tid == 0 && write_extras)
        out[(size_t)BB * SS * HH + 2 * BB * KSEL + b] = red[0] / (float)KSEL; // log_prob
}

// ============================================================================
// Kernel 3: zero selected rows (perturb value = TYPE_VALUES[1]*SCALE = 0.0)
// grid (KSEL, BB), 256 threads x 2 float4 = 8192 B/row
// ============================================================================
__global__ __launch_bounds__(256)
void k_zero(float* __restrict__ out)
{
    const int b   = blockIdx.y;
    const int row = d_sel[b * KSEL + blockIdx.x];
    float4* p = reinterpret_cast<float4*>(out + ((size_t)b * SS + row) * HH);
    const float4 z = make_float4(0.f, 0.f, 0.f, 0.f);
    p[threadIdx.x]       = z;
    p[threadIdx.x + 256] = z;
}

// ============================================================================
extern "C" void kernel_launch(void* const* d_in, const int* in_sizes, int n_in,
                              void* d_out, int out_size)
{
    const float* hs = (const float*)d_in[0];   // (8,4096,2048) fp32
    const float* nu = (const float*)d_in[1];   // (8,4096)      fp32
    const float* w1 = (const float*)d_in[2];   // (2048,64)
    const float* b1 = (const float*)d_in[3];   // (64,)
    const float* w2 = (const float*)d_in[4];   // (64,1)
    const float* b2 = (const float*)d_in[5];   // (1,)
    float* out = (float*)d_out;

    const long long need = (long long)BB * SS * HH + 2LL * BB * KSEL + BB;
    const int write_extras = ((long long)out_size >= need) ? 1 : 0;

    k_gemm<<<(BB * SS) / BM, 128>>>(hs, w1, b1, w2, b2, out);
    k_topk<<<BB, 512>>>(nu, out, write_extras);
    k_zero<<<dim3(KSEL, BB), 256>>>(out);
    (void)in_sizes; (void)n_in;
}

// round 4
// speedup vs baseline: 1.1160x; 1.1160x over previous
#include <cuda_runtime.h>
#include <cuda_fp16.h>

#define BB    8
#define SS    4096
#define HH    2048
#define DHH   64
#define KSEL  256
#define SPLIT 2
#define KHALF (HH / SPLIT)

// scratch (no cudaMalloc allowed)
__device__ float d_logits[BB * SS];
__device__ int   d_sel[BB * KSEL];
__device__ float d_cpart[SPLIT][BB * SS][DHH];   // 16MB split-K partials

__device__ __forceinline__ void fma2(unsigned long long& c,
                                     unsigned long long a,
                                     unsigned long long b) {
    asm("fma.rn.f32x2 %0, %1, %2, %0;" : "+l"(c) : "l"(a), "l"(b));
}

// fp32 value rounded through fp16 (matches reference .astype(float16) as fp32)
__device__ __forceinline__ float h16(float v) {
    return __half2float(__float2half_rn(v));
}

// ============================================================================
// Kernel 1: split-K GEMM partials (fp32 via packed f32x2 FMA) + fp16-rounded
// fp32 copy of hidden_states into out.
// grid (256, SPLIT): blockIdx.x = token tile (BM=128), blockIdx.y = K half.
// Thread (tx=tid&7, ty=tid>>3): 8 tokens x 8 cols as 4 packed f32x2 pairs.
// ============================================================================
constexpr int BM = 128, BK = 32;

__global__ __launch_bounds__(128, 4)
void k_gemm(const float* __restrict__ hs, const float* __restrict__ w1,
            float* __restrict__ out)
{
    __shared__ float2 a_s[BM][BK + 1];   // duplicated values, padded stride
    __shared__ float  b_s[BK][DHH];

    const int tid   = threadIdx.x;
    const int tx    = tid & 7;
    const int ty    = tid >> 3;
    const int tok0  = blockIdx.x * BM;
    const int kbase = blockIdx.y * KHALF;

    unsigned long long acc[8][4];
#pragma unroll
    for (int j = 0; j < 8; j++)
#pragma unroll
        for (int i = 0; i < 4; i++) acc[j][i] = 0ull;

    for (int k0 = kbase; k0 < kbase + KHALF; k0 += BK) {
        // stage A (128 x 32 fp32) + write fp16-rounded fp32 output
#pragma unroll
        for (int it = 0; it < 8; it++) {
            int idx = it * 128 + tid;
            int row = idx >> 3;
            int kk  = (idx & 7) << 2;
            const float4 v = *reinterpret_cast<const float4*>(
                hs + (size_t)(tok0 + row) * HH + k0 + kk);
            float4 ov = make_float4(h16(v.x), h16(v.y), h16(v.z), h16(v.w));
            *reinterpret_cast<float4*>(
                out + (size_t)(tok0 + row) * HH + k0 + kk) = ov;
            a_s[row][kk + 0] = make_float2(v.x, v.x);
            a_s[row][kk + 1] = make_float2(v.y, v.y);
            a_s[row][kk + 2] = make_float2(v.z, v.z);
            a_s[row][kk + 3] = make_float2(v.w, v.w);
        }
        // stage B (32 x 64 fp32)
#pragma unroll
        for (int it = 0; it < 4; it++) {
            int f  = (it * 128 + tid) * 4;
            int kk = f >> 6, c = f & 63;
            *reinterpret_cast<float4*>(&b_s[kk][c]) =
                *reinterpret_cast<const float4*>(w1 + (size_t)(k0 + kk) * DHH + c);
        }
        __syncthreads();

#pragma unroll
        for (int kk = 0; kk < BK; kk++) {
            unsigned long long bv[4];
            const unsigned long long* brow =
                reinterpret_cast<const unsigned long long*>(&b_s[kk][tx * 8]);
            bv[0] = brow[0]; bv[1] = brow[1]; bv[2] = brow[2]; bv[3] = brow[3];
#pragma unroll
            for (int j = 0; j < 8; j++) {
                unsigned long long av =
                    *reinterpret_cast<const unsigned long long*>(&a_s[j * 16 + ty][kk]);
                fma2(acc[j][0], av, bv[0]);
                fma2(acc[j][1], av, bv[1]);
                fma2(acc[j][2], av, bv[2]);
                fma2(acc[j][3], av, bv[3]);
            }
        }
        __syncthreads();
    }

    // write split-K partials (no reduction here; relu must wait for full sum)
#pragma unroll
    for (int j = 0; j < 8; j++) {
        float* dst = &d_cpart[blockIdx.y][tok0 + j * 16 + ty][tx * 8];
#pragma unroll
        for (int i = 0; i < 4; i++)
            *reinterpret_cast<unsigned long long*>(dst + 2 * i) = acc[j][i];
    }
}

// ============================================================================
// Kernel 1b: epilogue — sum split partials, +b1, relu, dot w2, +b2 -> logits.
// 256 threads: 16 tokens/block, 16 lanes per token (4 cols each, float4).
// ============================================================================
__global__ __launch_bounds__(256)
void k_epi(const float* __restrict__ b1, const float* __restrict__ w2,
           const float* __restrict__ b2)
{
    const int tid   = threadIdx.x;
    const int c16   = tid & 15;
    const int token = blockIdx.x * 16 + (tid >> 4);

    const float4 b1v = *reinterpret_cast<const float4*>(b1 + c16 * 4);
    const float4 w2v = *reinterpret_cast<const float4*>(w2 + c16 * 4);

    float4 v = *reinterpret_cast<const float4*>(&d_cpart[0][token][c16 * 4]);
#pragma unroll
    for (int s = 1; s < SPLIT; s++) {
        const float4 u = *reinterpret_cast<const float4*>(&d_cpart[s][token][c16 * 4]);
        v.x += u.x; v.y += u.y; v.z += u.z; v.w += u.w;
    }
    float p = fmaxf(v.x + b1v.x, 0.f) * w2v.x
            + fmaxf(v.y + b1v.y, 0.f) * w2v.y
            + fmaxf(v.z + b1v.z, 0.f) * w2v.z
            + fmaxf(v.w + b1v.w, 0.f) * w2v.w;
#pragma unroll
    for (int off = 8; off > 0; off >>= 1)
        p += __shfl_down_sync(0xffffffffu, p, off, 16);
    if (c16 == 0) d_logits[token] = p + b2[0];
}

// ============================================================================
// Kernel 2: per-batch gumbel top-k (full bitonic sort, matches jax.lax.top_k
// descending order + stable lowest-index tiebreak) + logsumexp + log_prob.
// ============================================================================
__global__ __launch_bounds__(512)
void k_topk(const float* __restrict__ noise, float* __restrict__ out,
            int write_extras)
{
    const int b   = blockIdx.x;
    const int tid = threadIdx.x;
    __shared__ unsigned long long keys[SS];
    __shared__ float red[512];

    const float* lg = d_logits + b * SS;
    const float* nu = noise    + b * SS;

    float m = -3.4e38f;
    for (int i = tid; i < SS; i += 512) {
        float l = lg[i];
        float s = l - logf(-logf(nu[i]));          // logit + gumbel
        unsigned u = __float_as_uint(s);
        u = (u & 0x80000000u) ? ~u : (u | 0x80000000u);
        keys[i] = ((unsigned long long)u << 32) | (unsigned)(~(unsigned)i);
        m = fmaxf(m, l);
    }
    red[tid] = m; __syncthreads();
    for (int s2 = 256; s2 > 0; s2 >>= 1) {
        if (tid < s2) red[tid] = fmaxf(red[tid], red[tid + s2]);
        __syncthreads();
    }
    m = red[0]; __syncthreads();
    float sum = 0.f;
    for (int i = tid; i < SS; i += 512) sum += expf(lg[i] - m);
    red[tid] = sum; __syncthreads();
    for (int s2 = 256; s2 > 0; s2 >>= 1) {
        if (tid < s2) red[tid] += red[tid + s2];
        __syncthreads();
    }
    const float lse = m + logf(red[0]);
    __syncthreads();

    for (int size = 2; size <= SS; size <<= 1) {
        for (int stride = size >> 1; stride > 0; stride >>= 1) {
            for (int t = tid; t < SS / 2; t += 512) {
                int i = 2 * t - (t & (stride - 1));
                int j = i + stride;
                bool desc = ((i & size) == 0);
                unsigned long long a = keys[i], c = keys[j];
                bool sw = desc ? (a < c) : (a > c);
                if (sw) { keys[i] = c; keys[j] = a; }
            }
            __syncthreads();
        }
    }

    float lp = 0.f;
    for (int kk = tid; kk < KSEL; kk += 512) {
        int idx = (int)(~(unsigned)(keys[kk] & 0xffffffffull));
        d_sel[b * KSEL + kk] = idx;
        lp += lg[idx] - lse;
        if (write_extras) {
            out[(size_t)BB * SS * HH + b * KSEL + kk] = (float)idx;           // indices
            out[(size_t)BB * SS * HH + BB * KSEL + b * KSEL + kk] = 1.0f;     // types
        }
    }
    red[tid] = lp; __syncthreads();
    for (int s2 = 256; s2 > 0; s2 >>= 1) {
        if (tid < s2) red[tid] += red[tid + s2];
        __syncthreads();
    }
    if (tid == 0 && write_extras)
        out[(size_t)BB * SS * HH + 2 * BB * KSEL + b] = red[0] / (float)KSEL; // log_prob
}

// ============================================================================
// Kernel 3: zero selected rows (perturb value = TYPE_VALUES[1]*SCALE = 0.0)
// ============================================================================
__global__ __launch_bounds__(256)
void k_zero(float* __restrict__ out)
{
    const int b   = blockIdx.y;
    const int row = d_sel[b * KSEL + blockIdx.x];
    float4* p = reinterpret_cast<float4*>(out + ((size_t)b * SS + row) * HH);
    const float4 z = make_float4(0.f, 0.f, 0.f, 0.f);
    p[threadIdx.x]       = z;
    p[threadIdx.x + 256] = z;
}

// ============================================================================
extern "C" void kernel_launch(void* const* d_in, const int* in_sizes, int n_in,
                              void* d_out, int out_size)
{
    const float* hs = (const float*)d_in[0];   // (8,4096,2048) fp32
    const float* nu = (const float*)d_in[1];   // (8,4096)      fp32
    const float* w1 = (const float*)d_in[2];   // (2048,64)
    const float* b1 = (const float*)d_in[3];   // (64,)
    const float* w2 = (const float*)d_in[4];   // (64,1)
    const float* b2 = (const float*)d_in[5];   // (1,)
    float* out = (float*)d_out;

    const long long need = (long long)BB * SS * HH + 2LL * BB * KSEL + BB;
    const int write_extras = ((long long)out_size >= need) ? 1 : 0;

    k_gemm<<<dim3((BB * SS) / BM, SPLIT), 128>>>(hs, w1, out);
    k_epi<<<(BB * SS) / 16, 256>>>(b1, w2, b2);
    k_topk<<<BB, 512>>>(nu, out, write_extras);
    k_zero<<<dim3(KSEL, BB), 256>>>(out);
    (void)in_sizes; (void)n_in;
}